// round 11
// baseline (speedup 1.0000x reference)
#include <cuda_runtime.h>

#define NTHREADS 512
#define TS 1028                  // tile row stride
#define ROWS 32

#define SM_TOTAL (32 * TS)       // 32896 floats = 131584 B

typedef unsigned long long u64;
typedef unsigned int u32;

// fragment-packed bf16 split weights: [layer*32+block][cell 16][lane 32] -> {h0,h1,l0,l1}
__device__ uint4 g_w1[2 * 32 * 16 * 32];
__device__ uint4 g_w2[2 * 32 * 16 * 32];

__device__ __forceinline__ u64 pack2(float lo, float hi) {
    u64 r; asm("mov.b64 %0, {%1, %2};" : "=l"(r) : "f"(lo), "f"(hi)); return r;
}
__device__ __forceinline__ void unpack2(u64 v, float& lo, float& hi) {
    asm("mov.b64 {%0, %1}, %2;" : "=f"(lo), "=f"(hi) : "l"(v));
}
__device__ __forceinline__ u32 bpack(float lo, float hi) {
    u32 r; asm("cvt.rn.bf16x2.f32 %0, %1, %2;" : "=r"(r) : "f"(hi), "f"(lo)); return r;
}
__device__ __forceinline__ float blof(u32 w) { return __uint_as_float(w << 16); }
__device__ __forceinline__ float bhif(u32 w) { return __uint_as_float(w & 0xFFFF0000u); }
__device__ __forceinline__ void bsplit2(float x0, float x1, u32& h, u32& l) {
    h = bpack(x0, x1);
    l = bpack(x0 - blof(h), x1 - bhif(h));
}
__device__ __forceinline__ void mma16(float* c, const u32* a, u32 b0, u32 b1) {
    asm volatile(
        "mma.sync.aligned.m16n8k16.row.col.f32.bf16.bf16.f32 "
        "{%0,%1,%2,%3}, {%4,%5,%6,%7}, {%8,%9}, {%0,%1,%2,%3};"
        : "+f"(c[0]), "+f"(c[1]), "+f"(c[2]), "+f"(c[3])
        : "r"(a[0]), "r"(a[1]), "r"(a[2]), "r"(a[3]), "r"(b0), "r"(b1));
}
__device__ __forceinline__ float elu(float v) {
    return v > 0.f ? v : (__expf(v) - 1.f);
}

// ---- prep: split weights into bf16 hi/lo, fragment-packed uint4 cells ----
__global__ void prep_kernel(
    const float* __restrict__ W1a, const float* __restrict__ W2a,
    const float* __restrict__ W1b, const float* __restrict__ W2b)
{
    int id = blockIdx.x * blockDim.x + threadIdx.x;   // 65536 total
    int lane = id & 31;
    int cell = (id >> 5) & 15;
    int b    = (id >> 9) & 31;
    int mat  = (id >> 14) & 1;
    int l    = (id >> 15) & 1;
    int g = lane >> 2, t4 = lane & 3;

    float f00, f01, f10, f11;
    if (mat == 0) {
        int nt = cell >> 1, kt = cell & 1;
        int k0 = kt * 16 + 2 * t4, n = nt * 8 + g;
        const float* W = (l ? W1b : W1a) + b * 2048;
        f00 = W[k0 * 64 + n];       f01 = W[(k0 + 1) * 64 + n];
        f10 = W[(k0 + 8) * 64 + n]; f11 = W[(k0 + 9) * 64 + n];
    } else {
        int nt = cell >> 2, kt = cell & 3;
        int k0 = kt * 16 + 2 * t4, n = nt * 8 + g;
        const float* W = (l ? W2b : W2a) + b * 2048;
        f00 = W[k0 * 32 + n];       f01 = W[(k0 + 1) * 32 + n];
        f10 = W[(k0 + 8) * 32 + n]; f11 = W[(k0 + 9) * 32 + n];
    }
    u32 h0, l0, h1, l1;
    bsplit2(f00, f01, h0, l0);
    bsplit2(f10, f11, h1, l1);
    uint4 v; v.x = h0; v.y = h1; v.z = l0; v.w = l1;
    uint4* dst = mat ? g_w2 : g_w1;
    dst[((l * 32 + b) * 16 + cell) * 32 + lane] = v;
}

// in-place per-row 32x32 block transpose; 16 warps x 2 rows = 32 rows
__device__ __forceinline__ void transpose_tile(float* tile, int warp, int lane) {
    const int a2 = lane >> 3;
    const int B  = lane & 7;
    #pragma unroll
    for (int rr = 0; rr < 2; ++rr) {
        float* row = tile + (warp * 2 + rr) * TS;
        float4 v[2][4];
        #pragma unroll
        for (int h = 0; h < 2; ++h) {
            int A = a2 + 4 * h;
            #pragma unroll
            for (int i = 0; i < 4; ++i)
                v[h][i] = *(const float4*)(row + 32 * (4 * A + i) + 4 * B);
        }
        __syncwarp();
        #pragma unroll
        for (int h = 0; h < 2; ++h) {
            int A = a2 + 4 * h;
            #pragma unroll
            for (int i = 0; i < 4; ++i) {
                float4 t;
                t.x = ((const float*)&v[h][0])[i];
                t.y = ((const float*)&v[h][1])[i];
                t.z = ((const float*)&v[h][2])[i];
                t.w = ((const float*)&v[h][3])[i];
                *(float4*)(row + 32 * (4 * B + i) + 4 * A) = t;
            }
        }
        __syncwarp();
    }
}

__global__ __launch_bounds__(NTHREADS, 1) void mixer_kernel(
    const float* __restrict__ x,
    const float* __restrict__ B1a, const float* __restrict__ B2a,
    const float* __restrict__ B1b, const float* __restrict__ B2b,
    float* __restrict__ out)
{
    extern __shared__ float smem[];
    float* tile = smem;

    const int tid  = threadIdx.x;
    const int warp = tid >> 5;
    const int lane = tid & 31;
    const int g    = lane >> 2;
    const int t4   = lane & 3;
    const long row0 = (long)blockIdx.x * ROWS;

    const float* B1p[2] = {B1a, B1b};
    const float* B2p[2] = {B2a, B2b};

    // ---- load x tile ----
    {
        const float4* src = (const float4*)(x + row0 * 1024);
        #pragma unroll
        for (int it = 0; it < 16; ++it) {
            int i = tid + it * NTHREADS;
            int r = i >> 8, c4 = i & 255;
            *(float4*)(tile + r * TS + c4 * 4) = src[r * 256 + c4];
        }
    }
    __syncthreads();

    #pragma unroll 1
    for (int si = 0; si < 4; ++si) {
        if (si == 2) {                        // layer boundary
            __syncthreads();
            transpose_tile(tile, warp, lane);
            __syncthreads();
        }
        const int layer = si >> 1;
        const int blk   = (si & 1) * 16 + warp;   // this warp's block
        const int lb    = layer * 32 + blk;
        const int cbase = blk * 32;

        const uint4* w1q = g_w1 + (size_t)lb * 512 + lane;
        const uint4* w2q = g_w2 + (size_t)lb * 512 + lane;

        // ---- A-fragments: bf16 split of x for both row-groups ----
        // rg r covers rows {g + 16r, g + 16r + 8}
        u32 xh[2][2][4], xl[2][2][4];
        #pragma unroll
        for (int rg = 0; rg < 2; ++rg) {
            const float* xr = tile + (g + rg * 16) * TS + cbase;
            #pragma unroll
            for (int kt = 0; kt < 2; ++kt) {
                int c0 = kt * 16 + 2 * t4;
                float2 v0 = *(const float2*)(xr + c0);
                float2 v1 = *(const float2*)(xr + 8 * TS + c0);
                float2 v2 = *(const float2*)(xr + c0 + 8);
                float2 v3 = *(const float2*)(xr + 8 * TS + c0 + 8);
                bsplit2(v0.x, v0.y, xh[rg][kt][0], xl[rg][kt][0]);
                bsplit2(v1.x, v1.y, xh[rg][kt][1], xl[rg][kt][1]);
                bsplit2(v2.x, v2.y, xh[rg][kt][2], xl[rg][kt][2]);
                bsplit2(v3.x, v3.y, xh[rg][kt][3], xl[rg][kt][3]);
            }
        }

        // ---- matmul1: 32 rows x 64 hidden, weights loaded once ----
        float c1[2][8][4];
        {
            const u64* b1q = (const u64*)(B1p[layer] + blk * 64);
            #pragma unroll
            for (int nt = 0; nt < 8; ++nt) {
                float blo, bhi;
                unpack2(b1q[nt * 4 + t4], blo, bhi);
                #pragma unroll
                for (int rg = 0; rg < 2; ++rg) {
                    c1[rg][nt][0] = blo; c1[rg][nt][1] = bhi;
                    c1[rg][nt][2] = blo; c1[rg][nt][3] = bhi;
                }
            }
        }
        #pragma unroll
        for (int nt = 0; nt < 8; ++nt) {
            uint4 B0 = w1q[(nt * 2 + 0) * 32];
            uint4 B1 = w1q[(nt * 2 + 1) * 32];
            #pragma unroll
            for (int rg = 0; rg < 2; ++rg) {
                mma16(c1[rg][nt], xh[rg][0], B0.x, B0.y);
                mma16(c1[rg][nt], xl[rg][0], B0.x, B0.y);
                mma16(c1[rg][nt], xh[rg][0], B0.z, B0.w);
                mma16(c1[rg][nt], xh[rg][1], B1.x, B1.y);
                mma16(c1[rg][nt], xl[rg][1], B1.x, B1.y);
                mma16(c1[rg][nt], xh[rg][1], B1.z, B1.w);
            }
        }

        // ---- ELU in registers, rebuild mm2 A-fragments directly ----
        u32 a2h[2][4][4], a2l[2][4][4];
        #pragma unroll
        for (int rg = 0; rg < 2; ++rg) {
            #pragma unroll
            for (int nt = 0; nt < 8; ++nt) {
                c1[rg][nt][0] = elu(c1[rg][nt][0]);
                c1[rg][nt][1] = elu(c1[rg][nt][1]);
                c1[rg][nt][2] = elu(c1[rg][nt][2]);
                c1[rg][nt][3] = elu(c1[rg][nt][3]);
            }
            #pragma unroll
            for (int kt = 0; kt < 4; ++kt) {
                bsplit2(c1[rg][2*kt][0],   c1[rg][2*kt][1],   a2h[rg][kt][0], a2l[rg][kt][0]);
                bsplit2(c1[rg][2*kt][2],   c1[rg][2*kt][3],   a2h[rg][kt][1], a2l[rg][kt][1]);
                bsplit2(c1[rg][2*kt+1][0], c1[rg][2*kt+1][1], a2h[rg][kt][2], a2l[rg][kt][2]);
                bsplit2(c1[rg][2*kt+1][2], c1[rg][2*kt+1][3], a2h[rg][kt][3], a2l[rg][kt][3]);
            }
        }

        // ---- matmul2: 32 rows x 32 out; bias LDG + residual LDS at init ----
        float c2[2][4][4];
        {
            const u64* b2q = (const u64*)(B2p[layer] + blk * 32);
            #pragma unroll
            for (int nt = 0; nt < 4; ++nt) {
                float blo, bhi;
                unpack2(b2q[nt * 4 + t4], blo, bhi);
                #pragma unroll
                for (int rg = 0; rg < 2; ++rg) {
                    const float* rp = tile + (g + rg * 16) * TS + cbase + nt * 8 + 2 * t4;
                    float r0l, r0h, r1l, r1h;
                    unpack2(*(const u64*)rp, r0l, r0h);
                    unpack2(*(const u64*)(rp + 8 * TS), r1l, r1h);
                    c2[rg][nt][0] = blo + r0l; c2[rg][nt][1] = bhi + r0h;
                    c2[rg][nt][2] = blo + r1l; c2[rg][nt][3] = bhi + r1h;
                }
            }
        }
        #pragma unroll
        for (int kt = 0; kt < 4; ++kt) {
            #pragma unroll
            for (int nt = 0; nt < 4; ++nt) {
                uint4 B = w2q[(nt * 4 + kt) * 32];
                #pragma unroll
                for (int rg = 0; rg < 2; ++rg) {
                    mma16(c2[rg][nt], a2h[rg][kt], B.x, B.y);
                    mma16(c2[rg][nt], a2l[rg][kt], B.x, B.y);
                    mma16(c2[rg][nt], a2h[rg][kt], B.z, B.w);
                }
            }
        }
        #pragma unroll
        for (int rg = 0; rg < 2; ++rg) {
            float* resp = tile + (g + rg * 16) * TS + cbase;
            #pragma unroll
            for (int nt = 0; nt < 4; ++nt) {
                *(u64*)(resp + nt * 8 + 2 * t4)          = pack2(c2[rg][nt][0], c2[rg][nt][1]);
                *(u64*)(resp + 8 * TS + nt * 8 + 2 * t4) = pack2(c2[rg][nt][2], c2[rg][nt][3]);
            }
        }
    }

    __syncthreads();
    transpose_tile(tile, warp, lane);        // undo layer-1 permutation
    __syncthreads();

    // ---- store output ----
    {
        float4* dst = (float4*)(out + row0 * 1024);
        #pragma unroll
        for (int it = 0; it < 16; ++it) {
            int i = tid + it * NTHREADS;
            int r = i >> 8, c4 = i & 255;
            dst[r * 256 + c4] = *(const float4*)(tile + r * TS + c4 * 4);
        }
    }
}

extern "C" void kernel_launch(void* const* d_in, const int* in_sizes, int n_in,
                              void* d_out, int out_size) {
    const float* x   = (const float*)d_in[0];
    const float* W1a = (const float*)d_in[1];
    const float* B1a = (const float*)d_in[2];
    const float* W2a = (const float*)d_in[3];
    const float* B2a = (const float*)d_in[4];
    const float* W1b = (const float*)d_in[5];
    const float* B1b = (const float*)d_in[6];
    const float* W2b = (const float*)d_in[7];
    const float* B2b = (const float*)d_in[8];
    float* out = (float*)d_out;

    int rows = in_sizes[0] / 1024;
    int grid = rows / ROWS;                    // 512

    size_t smem_bytes = (size_t)SM_TOTAL * sizeof(float);   // 131584 B
    static int configured = -1;
    if (configured < 0) {
        cudaFuncSetAttribute(mixer_kernel,
                             cudaFuncAttributeMaxDynamicSharedMemorySize,
                             (int)smem_bytes);
        configured = 1;
    }

    prep_kernel<<<256, 256>>>(W1a, W2a, W1b, W2b);
    mixer_kernel<<<grid, NTHREADS, smem_bytes>>>(
        x, B1a, B2a, B1b, B2b, out);
}